// round 15
// baseline (speedup 1.0000x reference)
#include <cuda_runtime.h>
#include <cuda_bf16.h>
#include <math.h>

// Problem constants
#define BB   2
#define SQ   1024
#define DM   1024
#define NH   16
#define DK   64
#define DFF  2048
#define NL   4

// ---------------------------------------------------------------------------
// Scratch (device globals — no allocation allowed)
// ---------------------------------------------------------------------------
__device__ __align__(16) float g_q[BB * SQ * DM];
__device__ __align__(16) float g_k[BB * SQ * DM];
__device__ __align__(16) float g_v[BB * SQ * DM];
__device__ __align__(16) float g_x[BB * SQ * DM];
__device__ __align__(16) float g_xr[BB * SQ * DM];   // tf32-rounded activations
__device__ __align__(16) float g_t[BB * SQ * DM];
__device__ __align__(16) float g_h[BB * SQ * DFF];
// tf32-pre-rounded, TRANSPOSED weights: [N][K] layout
__device__ __align__(16) float g_wq[NL * DM * DM];
__device__ __align__(16) float g_wk[NL * DM * DM];
__device__ __align__(16) float g_wv[NL * DM * DM];
__device__ __align__(16) float g_w1[NL * DM * DFF];
__device__ __align__(16) float g_w2[NL * DFF * DM];

// ---------------------------------------------------------------------------
// Helpers
// ---------------------------------------------------------------------------
__device__ __forceinline__ unsigned f2tf(float f) {
    unsigned u;
    asm("cvt.rna.tf32.f32 %0, %1;" : "=r"(u) : "f"(f));
    return u;
}
__device__ __forceinline__ float f2tf_f(float f) {
    return __uint_as_float(f2tf(f));
}

__device__ __forceinline__ void mma8(float* c, const unsigned* a, const unsigned* b) {
    asm volatile(
        "mma.sync.aligned.m16n8k8.row.col.f32.tf32.tf32.f32 "
        "{%0,%1,%2,%3},{%4,%5,%6,%7},{%8,%9},{%0,%1,%2,%3};\n"
        : "+f"(c[0]), "+f"(c[1]), "+f"(c[2]), "+f"(c[3])
        : "r"(a[0]), "r"(a[1]), "r"(a[2]), "r"(a[3]), "r"(b[0]), "r"(b[1]));
}

// ldmatrix x4 (b16 view): 4 8x8 b16 matrices = 4 8x4 tf32 matrices.
__device__ __forceinline__ void ldsm4(unsigned& r0, unsigned& r1,
                                      unsigned& r2, unsigned& r3, unsigned addr) {
    asm volatile(
        "ldmatrix.sync.aligned.m8n8.x4.shared.b16 {%0,%1,%2,%3}, [%4];\n"
        : "=r"(r0), "=r"(r1), "=r"(r2), "=r"(r3) : "r"(addr));
}

__device__ __forceinline__ void cpa16(float* smem_dst, const float* gsrc) {
    unsigned s = (unsigned)__cvta_generic_to_shared(smem_dst);
    asm volatile("cp.async.cg.shared.global [%0], [%1], 16;" :: "r"(s), "l"(gsrc));
}
__device__ __forceinline__ void cpa_commit() {
    asm volatile("cp.async.commit_group;" ::: "memory");
}
__device__ __forceinline__ void cpa_wait1() {
    asm volatile("cp.async.wait_group 1;" ::: "memory");
}
__device__ __forceinline__ void cpa_wait0() {
    asm volatile("cp.async.wait_group 0;" ::: "memory");
}

__device__ __forceinline__ float gelu_tanh_f(float x) {
    float x3 = x * x * x;
    return 0.5f * x * (1.0f + tanhf(0.7978845608028654f * (x + 0.044715f * x3)));
}

__device__ __forceinline__ float block_sum256(float v, float* sh) {
    #pragma unroll
    for (int o = 16; o; o >>= 1) v += __shfl_xor_sync(0xffffffffu, v, o);
    int w = threadIdx.x >> 5;
    if ((threadIdx.x & 31) == 0) sh[w] = v;
    __syncthreads();
    float r = (threadIdx.x < 8) ? sh[threadIdx.x] : 0.0f;
    if (threadIdx.x < 32) {
        #pragma unroll
        for (int o = 4; o; o >>= 1) r += __shfl_xor_sync(0xffffffffu, r, o);
        if (threadIdx.x == 0) sh[0] = r;
    }
    __syncthreads();
    r = sh[0];
    __syncthreads();
    return r;
}

// ---------------------------------------------------------------------------
// round_w: dst[i] = tf32_rna(src[i])  (float4 grid-stride) — used for x
// ---------------------------------------------------------------------------
__global__ void __launch_bounds__(256) round_w(
    const float4* __restrict__ src, float4* __restrict__ dst, int n4)
{
    for (int i = blockIdx.x * blockDim.x + threadIdx.x; i < n4;
         i += gridDim.x * blockDim.x) {
        float4 v = src[i];
        v.x = f2tf_f(v.x); v.y = f2tf_f(v.y);
        v.z = f2tf_f(v.z); v.w = f2tf_f(v.w);
        dst[i] = v;
    }
}

// ---------------------------------------------------------------------------
// transpose_round: src [z][R][C] -> dst [z][C][R], tf32-rounded.
// block (32,8), grid (C/32, R/32, z)
// ---------------------------------------------------------------------------
__global__ void __launch_bounds__(256) transpose_round(
    const float* __restrict__ src, float* __restrict__ dst, int R, int C)
{
    __shared__ float tile[32][33];
    long zoff = (long)blockIdx.z * R * C;
    const float* s = src + zoff;
    float* d = dst + zoff;
    int tx = threadIdx.x, ty = threadIdx.y;
    int r0 = blockIdx.y * 32, c0 = blockIdx.x * 32;
    #pragma unroll
    for (int i = 0; i < 32; i += 8)
        tile[ty + i][tx] = s[(long)(r0 + ty + i) * C + c0 + tx];
    __syncthreads();
    #pragma unroll
    for (int i = 0; i < 32; i += 8)
        d[(long)(c0 + ty + i) * R + r0 + tx] = f2tf_f(tile[tx][ty + i]);
}

// ===========================================================================
// GEMM variant A (round-9 proven): 128x64 tile, 256 threads. Used for PV.
// ===========================================================================
#define GEMM_SMEM_BYTES ((2 * 128 * 36 + 2 * 32 * 72) * 4)

__global__ void __launch_bounds__(256) gemm_pv(
    const float* __restrict__ Ain, const float* __restrict__ Bmin,
    float* __restrict__ Cin)
{
    const float* A;
    const float* Bm;
    float* C;
    {
        int z = blockIdx.z;
        int b = z >> 4;
        int h = z & 15;
        A  = Ain + (long)z * SQ * SQ;
        Bm = Bmin + (long)b * SQ * DM + h * DK;
        C  = Cin + (long)b * SQ * DM + h * DK;
    }
    extern __shared__ float dsm[];
    float* As = dsm;                 // [2][128][36]
    float* Bs = dsm + 2 * 128 * 36;  // [2][32][72]

    const int lda = SQ, ldb = DM, ldc = DM, K = SQ;
    int t = threadIdx.x;
    int lane = t & 31, w = t >> 5;
    int wm = w >> 1, wn = w & 1;
    int lq = lane >> 2, lr = lane & 3;
    int row0 = blockIdx.y * 128, col0 = blockIdx.x * 64;

    float acc[2][4][4];
    #pragma unroll
    for (int i = 0; i < 2; i++)
        #pragma unroll
        for (int j = 0; j < 4; j++)
            #pragma unroll
            for (int l = 0; l < 4; l++) acc[i][j][l] = 0.0f;

    int a_row = t >> 3;
    int a_kc  = (t & 7) * 4;
    int b_kr  = t >> 4;
    int b_nc  = (t & 15) * 4;

    #define LOAD_TILES(s, k0)                                                   \
        {                                                                       \
            _Pragma("unroll")                                                   \
            for (int i = 0; i < 4; i++) {                                       \
                int row = a_row + i * 32;                                       \
                cpa16(&As[(s) * 4608 + row * 36 + a_kc],                        \
                      &A[(long)(row0 + row) * lda + (k0) + a_kc]);              \
            }                                                                   \
            _Pragma("unroll")                                                   \
            for (int i = 0; i < 2; i++) {                                       \
                int kr = b_kr + i * 16;                                         \
                cpa16(&Bs[(s) * 2304 + kr * 72 + b_nc],                         \
                      &Bm[(long)((k0) + kr) * ldb + col0 + b_nc]);              \
            }                                                                   \
        }

    LOAD_TILES(0, 0);
    cpa_commit();

    int KT = K >> 5;
    for (int kt = 0; kt < KT; kt++) {
        int cur = kt & 1;
        if (kt + 1 < KT) {
            LOAD_TILES(cur ^ 1, (kt + 1) * 32);
            cpa_commit();
            cpa_wait1();
        } else {
            cpa_wait0();
        }
        __syncthreads();

        const float* Ac = &As[cur * 4608];
        const float* Bc = &Bs[cur * 2304];
        #pragma unroll
        for (int ks = 0; ks < 4; ks++) {
            int kb = ks * 8;
            unsigned a[2][4], bf[4][2];
            #pragma unroll
            for (int mi = 0; mi < 2; mi++) {
                int ar = wm * 32 + mi * 16 + lq;
                a[mi][0] = f2tf(Ac[ar * 36 + kb + lr]);
                a[mi][1] = f2tf(Ac[(ar + 8) * 36 + kb + lr]);
                a[mi][2] = f2tf(Ac[ar * 36 + kb + 4 + lr]);
                a[mi][3] = f2tf(Ac[(ar + 8) * 36 + kb + 4 + lr]);
            }
            #pragma unroll
            for (int nj = 0; nj < 4; nj++) {
                int bn = wn * 32 + nj * 8 + lq;
                bf[nj][0] = __float_as_uint(Bc[(kb + lr) * 72 + bn]);
                bf[nj][1] = __float_as_uint(Bc[(kb + 4 + lr) * 72 + bn]);
            }
            #pragma unroll
            for (int mi = 0; mi < 2; mi++)
                #pragma unroll
                for (int nj = 0; nj < 4; nj++)
                    mma8(acc[mi][nj], a[mi], bf[nj]);
        }
        __syncthreads();
    }
    #undef LOAD_TILES

    #pragma unroll
    for (int mi = 0; mi < 2; mi++) {
        #pragma unroll
        for (int nj = 0; nj < 4; nj++) {
            int r = row0 + wm * 32 + mi * 16 + lq;
            int c = col0 + wn * 32 + nj * 8 + 2 * lr;
            *(float2*)&C[(long)r * ldc + c] =
                make_float2(acc[mi][nj][0], acc[mi][nj][1]);
            *(float2*)&C[(long)(r + 8) * ldc + c] =
                make_float2(acc[mi][nj][2], acc[mi][nj][3]);
        }
    }
}

// ===========================================================================
// GEMM variant C + ldmatrix: 128x128 CTA, 128 threads = 4 warps (2x2),
// warp tile 64x64. A [M][K], Bt [N][K] (both pre-rounded tf32 values).
// Fragment loads via ldmatrix.x4 (32 LDSM per k-tile instead of 128 LDS).
// ===========================================================================
#define G64_SMEM_BYTES ((2 * 128 * 36 + 2 * 128 * 36) * 4)

template<int EPI, int RND>
__device__ __forceinline__ void gemm64_body(
    const float* __restrict__ A, const float* __restrict__ Bt,
    float* __restrict__ C, const float* __restrict__ bias,
    int K, int lda, int ldb, int ldc, float* dsm)
{
    float* As = dsm;                  // [2][128][36]
    float* Bs = dsm + 2 * 128 * 36;   // [2][128][36]

    int t = threadIdx.x;              // 128 threads
    int lane = t & 31, w = t >> 5;    // 4 warps
    int wm = w >> 1, wn = w & 1;      // 2 x 2
    int lq = lane >> 2, lr = lane & 3;
    int row0 = blockIdx.y * 128, col0 = blockIdx.x * 128;

    float acc[4][8][4];
    #pragma unroll
    for (int i = 0; i < 4; i++)
        #pragma unroll
        for (int j = 0; j < 8; j++)
            #pragma unroll
            for (int l = 0; l < 4; l++) acc[i][j][l] = 0.0f;

    int a_row = t >> 3;               // 0..15 (x8 -> 128)
    int a_kc  = (t & 7) * 4;

    // ldmatrix lane addressing: lanes 0-15 give rows of matrices 0/1
    // (m-rows base..base+15, k kb..kb+3); lanes 16-31 matrices 2/3 (k kb+4..7).
    const unsigned asu = (unsigned)__cvta_generic_to_shared(As);
    const unsigned bsu = (unsigned)__cvta_generic_to_shared(Bs);
    int lrow = lane & 15;
    int lk4  = (lane >> 4) << 2;
    unsigned aoff[4], boff[4];
    #pragma unroll
    for (int mi = 0; mi < 4; mi++)
        aoff[mi] = ((wm * 64 + mi * 16 + lrow) * 36 + lk4) * 4;
    #pragma unroll
    for (int pp = 0; pp < 4; pp++)
        boff[pp] = ((wn * 64 + pp * 16 + lrow) * 36 + lk4) * 4;

    #define LOAD_TILES(s, k0)                                                   \
        {                                                                       \
            _Pragma("unroll")                                                   \
            for (int i = 0; i < 8; i++) {                                       \
                int row = a_row + i * 16;                                       \
                cpa16(&As[(s) * 4608 + row * 36 + a_kc],                        \
                      &A[(long)(row0 + row) * lda + (k0) + a_kc]);              \
                cpa16(&Bs[(s) * 4608 + row * 36 + a_kc],                        \
                      &Bt[(long)(col0 + row) * ldb + (k0) + a_kc]);             \
            }                                                                   \
        }

    LOAD_TILES(0, 0);
    cpa_commit();

    int KT = K >> 5;
    for (int kt = 0; kt < KT; kt++) {
        int cur = kt & 1;
        cpa_wait0();
        __syncthreads();
        if (kt + 1 < KT) {
            LOAD_TILES(cur ^ 1, (kt + 1) * 32);
            cpa_commit();
        }

        unsigned stg = (unsigned)(cur * 4608 * 4);
        #pragma unroll
        for (int ks = 0; ks < 4; ks++) {
            unsigned kbb = (unsigned)(ks * 8 * 4);
            unsigned a[4][4], bq[4][4];
            #pragma unroll
            for (int mi = 0; mi < 4; mi++)
                ldsm4(a[mi][0], a[mi][1], a[mi][2], a[mi][3],
                      asu + stg + aoff[mi] + kbb);
            #pragma unroll
            for (int pp = 0; pp < 4; pp++)
                ldsm4(bq[pp][0], bq[pp][1], bq[pp][2], bq[pp][3],
                      bsu + stg + boff[pp] + kbb);
            // bq[pp]: r0 = n-tile 2pp (k lo), r1 = n-tile 2pp+1 (k lo),
            //         r2 = n-tile 2pp (k hi), r3 = n-tile 2pp+1 (k hi)
            #pragma unroll
            for (int mi = 0; mi < 4; mi++) {
                #pragma unroll
                for (int nj = 0; nj < 8; nj++) {
                    int pp = nj >> 1;
                    unsigned bb[2];
                    bb[0] = (nj & 1) ? bq[pp][1] : bq[pp][0];
                    bb[1] = (nj & 1) ? bq[pp][3] : bq[pp][2];
                    mma8(acc[mi][nj], a[mi], bb);
                }
            }
        }
    }
    #undef LOAD_TILES

    #pragma unroll
    for (int mi = 0; mi < 4; mi++) {
        #pragma unroll
        for (int nj = 0; nj < 8; nj++) {
            int r = row0 + wm * 64 + mi * 16 + lq;
            int c = col0 + wn * 64 + nj * 8 + 2 * lr;
            float v0 = acc[mi][nj][0], v1 = acc[mi][nj][1];
            float v2 = acc[mi][nj][2], v3 = acc[mi][nj][3];
            if (EPI >= 1) {
                float b0 = bias[c], b1 = bias[c + 1];
                v0 += b0; v1 += b1; v2 += b0; v3 += b1;
            }
            if (EPI == 2) {
                v0 = gelu_tanh_f(v0); v1 = gelu_tanh_f(v1);
                v2 = gelu_tanh_f(v2); v3 = gelu_tanh_f(v3);
            }
            if (RND) {
                v0 = f2tf_f(v0); v1 = f2tf_f(v1);
                v2 = f2tf_f(v2); v3 = f2tf_f(v3);
            }
            *(float2*)&C[(long)r * ldc + c] = make_float2(v0, v1);
            *(float2*)&C[(long)(r + 8) * ldc + c] = make_float2(v2, v3);
        }
    }
}

template<int EPI, int RND>
__global__ void __launch_bounds__(128) gemm64_tf32(
    const float* __restrict__ A, const float* __restrict__ Bt,
    float* __restrict__ C, const float* __restrict__ bias,
    int K, int lda, int ldb, int ldc)
{
    extern __shared__ float dsm[];
    gemm64_body<EPI, RND>(A, Bt, C, bias, K, lda, ldb, ldc, dsm);
}

// Merged QKV: blockIdx.z selects projection. Weights transposed [N][K].
__global__ void __launch_bounds__(128) gemm_qkv64(
    const float* __restrict__ A,
    const float* __restrict__ B0, const float* __restrict__ B1,
    const float* __restrict__ B2,
    float* __restrict__ C0, float* __restrict__ C1, float* __restrict__ C2)
{
    extern __shared__ float dsm[];
    int zz = blockIdx.z;
    const float* Bt = (zz == 0) ? B0 : (zz == 1) ? B1 : B2;
    float* C = (zz == 0) ? C0 : (zz == 1) ? C1 : C2;
    gemm64_body<0, 1>(A, Bt, C, nullptr, DM, DM, DM, DM, dsm);
}

// ---------------------------------------------------------------------------
// Fused scores + softmax (round-9 proven): register-resident scores.
// Block = (z, 16 q-rows) x 1024 keys. 256 threads = 8 warps.
// grid: (SQ/16, B*NH). 2 CTAs/SM (79KB smem).
// ---------------------------------------------------------------------------
#define SC3_SMEM_BYTES ((16 * 68 + 2 * 128 * 68 + 128 + 128 + 1024) * 4)

__global__ void __launch_bounds__(256, 2) attn_scores_softmax(
    const float* __restrict__ q, const float* __restrict__ k,
    const float* __restrict__ bias, const int* __restrict__ mask,
    float* __restrict__ p)
{
    extern __shared__ char smx[];
    unsigned* Qs = (unsigned*)smx;               // [16][68] tf32 bits
    float* Ks   = (float*)(Qs + 16 * 68);        // [2][128][68]
    float* rmax = Ks + 2 * 128 * 68;             // [16][8]
    float* rsum = rmax + 128;                    // [16][8]
    int*   msk  = (int*)(rsum + 128);            // [1024]

    int t = threadIdx.x;
    int lane = t & 31, w = t >> 5;               // 8 warps
    int lq = lane >> 2, lr = lane & 3;
    int z = blockIdx.y, b = z >> 4, h = z & 15;
    int q0 = blockIdx.x * 16;

    const float* qb = q + (long)b * SQ * DM + h * DK;
    const float* kb = k + (long)b * SQ * DM + h * DK;
    const float* bz = bias + (long)z * SQ * SQ;

    int k_row = t >> 4;
    int k_kc  = (t & 15) * 4;
    #define LOAD_SLAB(s, key0)                                                  \
        {                                                                       \
            _Pragma("unroll")                                                   \
            for (int i = 0; i < 8; i++) {                                       \
                int row = k_row + i * 16;                                       \
                cpa16(&Ks[(s) * 8704 + row * 68 + k_kc],                        \
                      &kb[(long)((key0) + row) * DM + k_kc]);                   \
            }                                                                   \
        }

    LOAD_SLAB(0, 0);
    cpa_commit();

    {
        int row = t >> 4;
        int kc = (t & 15) * 4;
        float4 vq = *(const float4*)&qb[(long)(q0 + row) * DM + kc];
        unsigned* dst = &Qs[row * 68 + kc];
        dst[0] = __float_as_uint(vq.x); dst[1] = __float_as_uint(vq.y);
        dst[2] = __float_as_uint(vq.z); dst[3] = __float_as_uint(vq.w);
    }
    ((int4*)msk)[t] = ((const int4*)(mask + b * SQ))[t];

    float sc[8][8];
    float m0 = -3.4e38f, m1 = -3.4e38f;

    const int c0b = w * 16 + 2 * lr;
    long row_a = (long)(q0 + lq) * SQ;
    long row_b = (long)(q0 + lq + 8) * SQ;

    #pragma unroll
    for (int slab = 0; slab < 8; slab++) {
        int cur = slab & 1;
        int key0 = slab * 128;
        if (slab + 1 < 8) {
            LOAD_SLAB(cur ^ 1, key0 + 128);
            cpa_commit();
        }
        int c0 = key0 + c0b;
        int c1 = c0 + 8;
        float2 B00 = *(const float2*)&bz[row_a + c0];
        float2 B01 = *(const float2*)&bz[row_a + c1];
        float2 B10 = *(const float2*)&bz[row_b + c0];
        float2 B11 = *(const float2*)&bz[row_b + c1];
        if (slab + 1 < 8) cpa_wait1(); else cpa_wait0();
        __syncthreads();

        #pragma unroll
        for (int j = 0; j < 8; j++) sc[slab][j] = 0.0f;

        const float* Kc = &Ks[cur * 8704];
        #pragma unroll
        for (int ks = 0; ks < 8; ks++) {
            int kv = ks * 8;
            unsigned a[4], bf0[2], bf1[2];
            a[0] = Qs[lq * 68 + kv + lr];
            a[1] = Qs[(lq + 8) * 68 + kv + lr];
            a[2] = Qs[lq * 68 + kv + 4 + lr];
            a[3] = Qs[(lq + 8) * 68 + kv + 4 + lr];
            int kn0 = w * 16 + lq;
            bf0[0] = __float_as_uint(Kc[kn0 * 68 + kv + lr]);
            bf0[1] = __float_as_uint(Kc[kn0 * 68 + kv + 4 + lr]);
            bf1[0] = __float_as_uint(Kc[(kn0 + 8) * 68 + kv + lr]);
            bf1[1] = __float_as_uint(Kc[(kn0 + 8) * 68 + kv + 4 + lr]);
            mma8(&sc[slab][0], a, bf0);
            mma8(&sc[slab][4], a, bf1);
        }

        int mk0a = msk[c0], mk0b = msk[c0 + 1];
        int mk1a = msk[c1], mk1b = msk[c1 + 1];
        float v0 = sc[slab][0] * 0.125f + B00.x; if (mk0a == 0) v0 = -9e15f;
        float v1 = sc[slab][1] * 0.125f + B00.y; if (mk0b == 0) v1 = -9e15f;
        float v2 = sc[slab][2] * 0.125f + B10.x; if (mk0a == 0) v2 = -9e15f;
        float v3 = sc[slab][3] * 0.125f + B10.y; if (mk0b == 0) v3 = -9e15f;
        float v4 = sc[slab][4] * 0.125f + B01.x; if (mk1a == 0) v4 = -9e15f;
        float v5 = sc[slab][5] * 0.125f + B01.y; if (mk1b == 0) v5 = -9e15f;
        float v6 = sc[slab][6] * 0.125f + B11.x; if (mk1a == 0) v6 = -9e15f;
        float v7 = sc[slab][7] * 0.125f + B11.y; if (mk1b == 0) v7 = -9e15f;
        sc[slab][0] = v0; sc[slab][1] = v1; sc[slab][2] = v2; sc[slab][3] = v3;
        sc[slab][4] = v4; sc[slab][5] = v5; sc[slab][6] = v6; sc[slab][7] = v7;
        m0 = fmaxf(m0, fmaxf(fmaxf(v0, v1), fmaxf(v4, v5)));
        m1 = fmaxf(m1, fmaxf(fmaxf(v2, v3), fmaxf(v6, v7)));
        __syncthreads();
    }
    #undef LOAD_SLAB

    m0 = fmaxf(m0, __shfl_xor_sync(0xffffffffu, m0, 1));
    m0 = fmaxf(m0, __shfl_xor_sync(0xffffffffu, m0, 2));
    m1 = fmaxf(m1, __shfl_xor_sync(0xffffffffu, m1, 1));
    m1 = fmaxf(m1, __shfl_xor_sync(0xffffffffu, m1, 2));
    if (lr == 0) {
        rmax[lq * 8 + w] = m0;
        rmax[(lq + 8) * 8 + w] = m1;
    }
    __syncthreads();
    float rm0 = rmax[lq * 8];
    float rm1 = rmax[(lq + 8) * 8];
    #pragma unroll
    for (int j = 1; j < 8; j++) {
        rm0 = fmaxf(rm0, rmax[lq * 8 + j]);
        rm1 = fmaxf(rm1, rmax[(lq + 8) * 8 + j]);
    }

    float s0 = 0.0f, s1 = 0.0f;
    #pragma unroll
    for (int slab = 0; slab < 8; slab++) {
        float e0 = __expf(sc[slab][0] - rm0);
        float e1 = __expf(sc[slab][1] - rm0);
        float e4 = __expf(sc[slab][4] - rm0);
        float e5 = __expf(sc[slab][5] - rm0);
        float e2 = __expf(sc[slab][2] - rm1);
        float e3 = __expf(sc[slab][3] - rm1);
        float e6 = __expf(sc[slab][6] - rm1);
        float e7 = __expf(sc[slab][7] - rm1);
        s0 += (e0 + e1) + (e4 + e5);
        s1 += (e2 + e3) + (e6 + e7);
        sc[slab][0] = e0; sc[slab][1] = e1; sc[slab][2] = e2; sc[slab][3] = e3;
        sc[slab][4] = e4; sc[slab][5] = e5; sc[slab][6] = e6; sc[slab][7] = e7;
    }
    s0 += __shfl_xor_sync(0xffffffffu, s0, 1);
    s0 += __shfl_xor_sync(0xffffffffu, s0, 2);
    s1 += __shfl_xor_sync(0xffffffffu, s1, 1);
    s1 += __shfl_xor_sync(0xffffffffu, s1, 2);
    if (lr == 0) {
        rsum[lq * 8 + w] = s0;
        rsum[(lq + 8) * 8 + w] = s1;
    }
    __syncthreads();
    float t0 = 0.0f, t1 = 0.0f;
    #pragma unroll
    for (int j = 0; j < 8; j++) {
        t0 += rsum[lq * 8 + j];
        t1 += rsum[(lq + 8) * 8 + j];
    }
    float inv0 = 1.0f / t0;
    float inv1 = 1.0f / t1;

    float* pr0 = p + (long)z * SQ * SQ + row_a;
    float* pr1 = p + (long)z * SQ * SQ + row_b;
    #pragma unroll
    for (int slab = 0; slab < 8; slab++) {
        int c0 = slab * 128 + c0b;
        int c1 = c0 + 8;
        *(float2*)&pr0[c0] = make_float2(sc[slab][0] * inv0, sc[slab][1] * inv0);
        *(float2*)&pr0[c1] = make_float2(sc[slab][4] * inv0, sc[slab][5] * inv0);
        *(float2*)&pr1[c0] = make_float2(sc[slab][2] * inv1, sc[slab][3] * inv1);
        *(float2*)&pr1[c1] = make_float2(sc[slab][6] * inv1, sc[slab][7] * inv1);
    }
}

// ---------------------------------------------------------------------------
// resid_ln: out = LayerNorm(A + Bx)*g + b (full) ; out_r = tf32_rna(out)
// ---------------------------------------------------------------------------
__global__ void __launch_bounds__(256) resid_ln(
    const float* __restrict__ A, const float* __restrict__ Bx,
    const float* __restrict__ gw, const float* __restrict__ bw,
    float* __restrict__ out, float* __restrict__ out_r)
{
    __shared__ float sh[8];
    long base = (long)blockIdx.x * DM;
    int t = threadIdx.x;
    float4 a = *(const float4*)&A[base + t * 4];
    float4 b = *(const float4*)&Bx[base + t * 4];
    float4 v = make_float4(a.x + b.x, a.y + b.y, a.z + b.z, a.w + b.w);

    float s = block_sum256(v.x + v.y + v.z + v.w, sh);
    float mu = s * (1.0f / DM);
    float dx = v.x - mu, dy = v.y - mu, dz = v.z - mu, dw = v.w - mu;
    float ss = block_sum256(dx * dx + dy * dy + dz * dz + dw * dw, sh);
    float rstd = rsqrtf(ss * (1.0f / DM) + 1e-6f);

    float4 g4 = *(const float4*)&gw[t * 4];
    float4 b4 = *(const float4*)&bw[t * 4];
    float4 o;
    o.x = dx * rstd * g4.x + b4.x;
    o.y = dy * rstd * g4.y + b4.y;
    o.z = dz * rstd * g4.z + b4.z;
    o.w = dw * rstd * g4.w + b4.w;
    *(float4*)&out[base + t * 4] = o;
    float4 orr = make_float4(f2tf_f(o.x), f2tf_f(o.y), f2tf_f(o.z), f2tf_f(o.w));
    *(float4*)&out_r[base + t * 4] = orr;
}

// ---------------------------------------------------------------------------
// Launch
// ---------------------------------------------------------------------------
extern "C" void kernel_launch(void* const* d_in, const int* in_sizes, int n_in,
                              void* d_out, int out_size)
{
    const float* x_in      = (const float*)d_in[0];
    const int*   mask      = (const int*)  d_in[1];
    const float* attn_bias = (const float*)d_in[2];
    const float* Wq        = (const float*)d_in[3];
    const float* Wk        = (const float*)d_in[4];
    const float* Wv        = (const float*)d_in[5];
    const float* ln1_g     = (const float*)d_in[6];
    const float* ln1_b     = (const float*)d_in[7];
    const float* W1        = (const float*)d_in[8];
    const float* b1        = (const float*)d_in[9];
    const float* W2        = (const float*)d_in[10];
    const float* b2        = (const float*)d_in[11];
    const float* ln2_g     = (const float*)d_in[12];
    const float* ln2_b     = (const float*)d_in[13];

    float* out  = (float*)d_out;
    float* outx = out + (long)NL * BB * NH * SQ * SQ;

    float *gq, *gk, *gv, *gx, *gxr, *gt, *gh;
    float *wqT, *wkT, *wvT, *w1T, *w2T;
    cudaGetSymbolAddress((void**)&gq, g_q);
    cudaGetSymbolAddress((void**)&gk, g_k);
    cudaGetSymbolAddress((void**)&gv, g_v);
    cudaGetSymbolAddress((void**)&gx, g_x);
    cudaGetSymbolAddress((void**)&gxr, g_xr);
    cudaGetSymbolAddress((void**)&gt, g_t);
    cudaGetSymbolAddress((void**)&gh, g_h);
    cudaGetSymbolAddress((void**)&wqT, g_wq);
    cudaGetSymbolAddress((void**)&wkT, g_wk);
    cudaGetSymbolAddress((void**)&wvT, g_wv);
    cudaGetSymbolAddress((void**)&w1T, g_w1);
    cudaGetSymbolAddress((void**)&w2T, g_w2);

    static int smem_set = 0;
    if (!smem_set) {
        cudaFuncSetAttribute(attn_scores_softmax,
                             cudaFuncAttributeMaxDynamicSharedMemorySize, SC3_SMEM_BYTES);
        cudaFuncSetAttribute(gemm_qkv64,
                             cudaFuncAttributeMaxDynamicSharedMemorySize, G64_SMEM_BYTES);
        cudaFuncSetAttribute(gemm64_tf32<2, 1>,
                             cudaFuncAttributeMaxDynamicSharedMemorySize, G64_SMEM_BYTES);
        cudaFuncSetAttribute(gemm64_tf32<1, 0>,
                             cudaFuncAttributeMaxDynamicSharedMemorySize, G64_SMEM_BYTES);
        cudaFuncSetAttribute(gemm_pv,
                             cudaFuncAttributeMaxDynamicSharedMemorySize, GEMM_SMEM_BYTES);
        smem_set = 1;
    }

    // Pre-process: transpose+round weights to [N][K]; round x
    {
        dim3 tb(32, 8);
        transpose_round<<<dim3(DM / 32, DM / 32, NL), tb>>>(Wq, wqT, DM, DM);
        transpose_round<<<dim3(DM / 32, DM / 32, NL), tb>>>(Wk, wkT, DM, DM);
        transpose_round<<<dim3(DM / 32, DM / 32, NL), tb>>>(Wv, wvT, DM, DM);
        transpose_round<<<dim3(DFF / 32, DM / 32, NL), tb>>>(W1, w1T, DM, DFF);
        transpose_round<<<dim3(DM / 32, DFF / 32, NL), tb>>>(W2, w2T, DFF, DM);
        round_w<<<512, 256>>>((const float4*)x_in, (float4*)gxr, BB * SQ * DM / 4);
    }

    cudaMemcpyAsync(gx, x_in, sizeof(float) * BB * SQ * DM, cudaMemcpyDeviceToDevice);

    const int M = BB * SQ;  // 2048

    for (int n = 0; n < NL; n++) {
        float* p = out + (long)n * BB * NH * SQ * SQ;

        // QKV projections (A = rounded activations, Bt transposed weights)
        gemm_qkv64<<<dim3(8, 16, 3), dim3(128), G64_SMEM_BYTES>>>(
            gxr, wqT + (long)n * DM * DM, wkT + (long)n * DM * DM,
            wvT + (long)n * DM * DM, gq, gk, gv);

        // fused scores + softmax -> p (written once)
        attn_scores_softmax<<<dim3(SQ / 16, BB * NH), dim3(256), SC3_SMEM_BYTES>>>(
            gq, gk, attn_bias, mask, p);

        // o = p @ v (A=p full precision, cvt at fragment load)
        gemm_pv<<<dim3(1, SQ / 128, BB * NH), dim3(256), GEMM_SMEM_BYTES>>>(
            p, gv, gt);

        // x = LN(o + x)  (full + rounded)
        resid_ln<<<M, dim3(256)>>>(gt, gx,
            ln1_g + (long)n * DM, ln1_b + (long)n * DM, gx, gxr);

        // h = gelu(x W1 + b1); h rounded
        gemm64_tf32<2, 1><<<dim3(16, 16), dim3(128), G64_SMEM_BYTES>>>(
            gxr, w1T + (long)n * DM * DFF, gh, b1 + (long)n * DFF,
            DM, DM, DM, DFF);

        // f = h W2 + b2
        gemm64_tf32<1, 0><<<dim3(8, 16), dim3(128), G64_SMEM_BYTES>>>(
            gh, w2T + (long)n * DFF * DM, gt, b2 + (long)n * DM,
            DFF, DFF, DFF, DM);

        // x = LN(x + f)  (full + rounded)
        resid_ln<<<M, dim3(256)>>>(gx, gt,
            ln2_g + (long)n * DM, ln2_b + (long)n * DM, gx, gxr);
    }

    cudaMemcpyAsync(outx, gx, sizeof(float) * BB * SQ * DM, cudaMemcpyDeviceToDevice);
}